// round 8
// baseline (speedup 1.0000x reference)
#include <cuda_runtime.h>
#include <cstdint>

#define B_   256
#define T_   100
#define NIN  700
#define KP   704            // NIN padded to multiple of 16
#define NN   2068
#define NNP  2176           // NN padded to multiple of 128
#define NOUT 20
#define TAU  0.6f
#define KC   320            // Eigen kc panel size
#define MROWS (B_ * T_)     // 25600

#define BM 128
#define BN 128
#define BK 16

#define TILES_PER_T 102u    // 3 slabs x 17 col-blocks x 2 row-halves
#define NTILES      10200u  // 100 * 102
#define NHELP       40      // pure-GEMM helper CTAs

#define CPT 9               // steps: j=0..7 full, j=8 only tid<20
#define NWP 8

// ---------------- scratch (device globals; no runtime allocation) ----------
__device__ float g_ffp[3][(size_t)MROWS * NNP];  // per-panel ff partials
__device__ float g_xp[(size_t)MROWS * KP];       // x staged: [r = t*B+b][k], zero-padded
__device__ float g_w1t[(size_t)KP * NNP];        // W_fc1^T zero-padded: [k][n]
__device__ unsigned g_next;                      // GEMM tile steal counter
__device__ unsigned g_done[T_];                  // per-timestep completed-tile count

// ---------------- staging ---------------------------------------------------
__global__ void zero_ctrl_kernel() {
    int i = threadIdx.x;
    if (i < T_) g_done[i] = 0u;
    if (i == T_) g_next = 0u;
}

__global__ void pad_x_kernel(const float* __restrict__ x) {
    size_t idx = (size_t)blockIdx.x * blockDim.x + threadIdx.x;
    if (idx < (size_t)MROWS * KP) {
        int r = (int)(idx / KP);
        int k = (int)(idx - (size_t)r * KP);
        int t = r >> 8;                 // r = t*256 + b
        int b = r & 255;
        g_xp[idx] = (k < NIN) ? x[((size_t)b * T_ + t) * NIN + k] : 0.0f;
    }
}

__global__ void pad_w1t_kernel(const float* __restrict__ W1) {
    size_t idx = (size_t)blockIdx.x * blockDim.x + threadIdx.x;
    if (idx < (size_t)KP * NNP) {
        int k = (int)(idx / NNP);
        int n = (int)(idx - (size_t)k * NNP);
        g_w1t[idx] = (k < NIN && n < NN) ? W1[(size_t)n * NIN + k] : 0.0f;
    }
}

// ---------------- shared memory union ----------------------------------------
union SMem {
    struct { float As[2][BK][BM]; float Bs[2][BK][BN]; } g;   // 32 KB (GEMM tile)
    struct { int list[NN]; int wcnt[CPT][NWP]; } s;           // ~8.6 KB (steps)
};

// ---------------- one GEMM tile (R6 double-buffered FFMA body) ----------------
// tile n -> timestep tt, slab z, col block, row half. Values independent of
// schedule: per output element one sequential-k FMA chain (Eigen in-panel order).
__device__ __forceinline__ void do_tile(unsigned n, SMem* sm, int tid) {
    unsigned tt = n / TILES_PER_T;
    unsigned r  = n % TILES_PER_T;
    unsigned z  = r / 34u;
    unsigned r2 = r % 34u;
    int col0 = (int)(r2 >> 1) * BN;
    int row0 = (int)tt * 256 + (int)(r2 & 1u) * BM;
    int k0g  = (int)z * KC;
    int KL   = (z == 2u) ? (KP - 2 * KC) : KC;
    int nT   = KL / BK;

    float* C = g_ffp[0] + (size_t)z * MROWS * NNP;

    int arow = tid >> 1;
    int asub = (tid & 1) * 8;
    const float* ap = g_xp + (size_t)(row0 + arow) * KP + k0g + asub;

    int bn   = tid & 127;
    int bsub = (tid >> 7) * 8;
    const float* bp = g_w1t + (size_t)(k0g + bsub) * NNP + (col0 + bn);

    int tr = (tid >> 4) * 8;
    int tc = (tid & 15) * 8;

    float4 ra0, ra1;
    float  rbv[8];

    ra0 = *(const float4*)(ap);
    ra1 = *(const float4*)(ap + 4);
    #pragma unroll
    for (int i = 0; i < 8; i++) rbv[i] = bp[(size_t)i * NNP];

    sm->g.As[0][asub + 0][arow] = ra0.x; sm->g.As[0][asub + 1][arow] = ra0.y;
    sm->g.As[0][asub + 2][arow] = ra0.z; sm->g.As[0][asub + 3][arow] = ra0.w;
    sm->g.As[0][asub + 4][arow] = ra1.x; sm->g.As[0][asub + 5][arow] = ra1.y;
    sm->g.As[0][asub + 6][arow] = ra1.z; sm->g.As[0][asub + 7][arow] = ra1.w;
    #pragma unroll
    for (int i = 0; i < 8; i++) sm->g.Bs[0][bsub + i][bn] = rbv[i];
    __syncthreads();

    float acc[8][8];
    #pragma unroll
    for (int i = 0; i < 8; i++)
        #pragma unroll
        for (int j = 0; j < 8; j++) acc[i][j] = 0.0f;

    for (int tI = 0; tI < nT; tI++) {
        int  buf  = tI & 1;
        bool more = (tI + 1 < nT);

        if (more) {
            const float* apn = ap + (tI + 1) * BK;
            ra0 = *(const float4*)(apn);
            ra1 = *(const float4*)(apn + 4);
            const float* bpn = bp + (size_t)(tI + 1) * BK * NNP;
            #pragma unroll
            for (int i = 0; i < 8; i++) rbv[i] = bpn[(size_t)i * NNP];
        }

        #pragma unroll
        for (int kk = 0; kk < BK; kk++) {
            float a[8], bv[8];
            *(float4*)&a[0]  = *(const float4*)&sm->g.As[buf][kk][tr];
            *(float4*)&a[4]  = *(const float4*)&sm->g.As[buf][kk][tr + 4];
            *(float4*)&bv[0] = *(const float4*)&sm->g.Bs[buf][kk][tc];
            *(float4*)&bv[4] = *(const float4*)&sm->g.Bs[buf][kk][tc + 4];
            #pragma unroll
            for (int i = 0; i < 8; i++)
                #pragma unroll
                for (int j = 0; j < 8; j++)
                    acc[i][j] = __fmaf_rn(a[i], bv[j], acc[i][j]);
        }

        if (more) {
            int nb = buf ^ 1;
            sm->g.As[nb][asub + 0][arow] = ra0.x; sm->g.As[nb][asub + 1][arow] = ra0.y;
            sm->g.As[nb][asub + 2][arow] = ra0.z; sm->g.As[nb][asub + 3][arow] = ra0.w;
            sm->g.As[nb][asub + 4][arow] = ra1.x; sm->g.As[nb][asub + 5][arow] = ra1.y;
            sm->g.As[nb][asub + 6][arow] = ra1.z; sm->g.As[nb][asub + 7][arow] = ra1.w;
            #pragma unroll
            for (int i = 0; i < 8; i++) sm->g.Bs[nb][bsub + i][bn] = rbv[i];
        }
        __syncthreads();
    }

    #pragma unroll
    for (int i = 0; i < 8; i++) {
        float* crow = C + (size_t)(row0 + tr + i) * NNP + (col0 + tc);
        *(float4*)(crow)     = *(float4*)&acc[i][0];
        *(float4*)(crow + 4) = *(float4*)&acc[i][4];
    }

    __threadfence();            // release this thread's C stores
    __syncthreads();
    if (tid == 0) atomicAdd(&g_done[tt], 1u);
}

// ---------------- fused persistent kernel ------------------------------------
// bid < 256: batch CTA (steps + help GEMM while waiting). bid >= 256: helper.
__global__ __launch_bounds__(256, 2) void fused_kernel(const float* __restrict__ Wrec,
                                                       float* __restrict__ out) {
    __shared__ SMem sm;
    __shared__ unsigned sc_ready;
    __shared__ unsigned sc_tile;

    int bid  = blockIdx.x;
    int tid  = threadIdx.x;

    if (bid >= B_) {
        // pure GEMM helper: drain the tile queue, then exit
        for (;;) {
            if (tid == 0) sc_tile = atomicAdd(&g_next, 1u);
            __syncthreads();
            unsigned n = sc_tile;
            __syncthreads();
            if (n >= NTILES) return;
            do_tile(n, &sm, tid);
        }
    }

    // ---- batch CTA ----
    int b    = bid;
    int wid  = tid >> 5;
    int lane = tid & 31;
    unsigned ltmask = (1u << lane) - 1u;
    bool tv  = (tid < NOUT);

    float m[CPT], s[CPT];
    #pragma unroll
    for (int j = 0; j < CPT; j++) { m[j] = 0.0f; s[j] = 0.0f; }

    const float* ff0 = g_ffp[0];
    const float* ff1 = g_ffp[1];
    const float* ff2 = g_ffp[2];

    for (int t = 0; t < T_; t++) {
        // ---- wait for ff[t]; help with GEMM tiles meanwhile ----
        for (;;) {
            if (tid == 0)
                sc_ready = (*(volatile unsigned*)&g_done[t] >= TILES_PER_T) ? 1u : 0u;
            __syncthreads();
            if (sc_ready) break;
            if (tid == 0) sc_tile = atomicAdd(&g_next, 1u);
            __syncthreads();
            unsigned n = sc_tile;
            if (n < NTILES) do_tile(n, &sm, tid);   // ends with __syncthreads()
            else            __nanosleep(256);
            __syncthreads();
        }
        __threadfence();   // acquire: order ff loads after observed completion

        // ---- ff partial fold: ff = (p0 + p1) + p2 ----
        size_t rbase = ((size_t)t * B_ + b) * NNP;
        float ffv[CPT];
        #pragma unroll
        for (int j = 0; j < CPT; j++) {
            int n = j * 256 + tid;
            bool v = (j < 8) || tv;
            ffv[j] = v ? __fadd_rn(__fadd_rn(ff0[rbase + n], ff1[rbase + n]), ff2[rbase + n])
                       : 0.0f;
        }

        // ---- build ascending active list (ballot + cross-warp prefix) ----
        unsigned msk[CPT];
        #pragma unroll
        for (int j = 0; j < CPT; j++) {
            bool a = ((j < 8) || tv) && (s[j] != 0.0f);
            msk[j] = __ballot_sync(0xffffffffu, a);
            if (lane == 0) sm.s.wcnt[j][wid] = __popc(msk[j]);
        }
        __syncthreads();

        int base[CPT];
        int cnt;
        {
            int rb = 0;
            #pragma unroll
            for (int jj = 0; jj < CPT; jj++) {
                int off = 0, rowtot = 0;
                #pragma unroll
                for (int w = 0; w < NWP; w++) {
                    int c = sm.s.wcnt[jj][w];
                    if (w < wid) off += c;
                    rowtot += c;
                }
                base[jj] = rb + off;
                rb += rowtot;
            }
            cnt = rb;
        }

        #pragma unroll
        for (int j = 0; j < CPT; j++) {
            bool a = ((j < 8) || tv) && (s[j] != 0.0f);
            if (a) sm.s.list[base[j] + __popc(msk[j] & ltmask)] = j * 256 + tid;
        }
        __syncthreads();

        // ---- rec: kc=320-panel fold of ascending active-row adds (unroll-2) ----
        float rec[CPT], part[CPT];
        #pragma unroll
        for (int j = 0; j < CPT; j++) { rec[j] = 0.0f; part[j] = 0.0f; }

        int curp = 0;
        int i = 0;
        for (; i + 2 <= cnt; i += 2) {
            int m0 = sm.s.list[i + 0], m1 = sm.s.list[i + 1];
            const float* w0 = Wrec + (size_t)m0 * NN;
            const float* w1 = Wrec + (size_t)m1 * NN;
            float v0[CPT], v1[CPT];
            #pragma unroll
            for (int j = 0; j < CPT; j++) {
                int n = j * 256 + tid;
                bool v = (j < 8) || tv;
                v0[j] = v ? w0[n] : 0.0f;
                v1[j] = v ? w1[n] : 0.0f;
            }
            int p;
            p = m0 / KC;
            if (p != curp) {
                #pragma unroll
                for (int j = 0; j < CPT; j++) { rec[j] = __fadd_rn(rec[j], part[j]); part[j] = 0.0f; }
                curp = p;
            }
            #pragma unroll
            for (int j = 0; j < CPT; j++) part[j] = __fadd_rn(part[j], v0[j]);
            p = m1 / KC;
            if (p != curp) {
                #pragma unroll
                for (int j = 0; j < CPT; j++) { rec[j] = __fadd_rn(rec[j], part[j]); part[j] = 0.0f; }
                curp = p;
            }
            #pragma unroll
            for (int j = 0; j < CPT; j++) part[j] = __fadd_rn(part[j], v1[j]);
        }
        for (; i < cnt; i++) {
            int mr = sm.s.list[i];
            const float* wr = Wrec + (size_t)mr * NN;
            float v0[CPT];
            #pragma unroll
            for (int j = 0; j < CPT; j++) {
                int n = j * 256 + tid;
                v0[j] = ((j < 8) || tv) ? wr[n] : 0.0f;
            }
            int p = mr / KC;
            if (p != curp) {
                #pragma unroll
                for (int j = 0; j < CPT; j++) { rec[j] = __fadd_rn(rec[j], part[j]); part[j] = 0.0f; }
                curp = p;
            }
            #pragma unroll
            for (int j = 0; j < CPT; j++) part[j] = __fadd_rn(part[j], v0[j]);
        }
        #pragma unroll
        for (int j = 0; j < CPT; j++) rec[j] = __fadd_rn(rec[j], part[j]);  // final fold

        // ---- membrane update + spikes (unfused, reference order) ----
        #pragma unroll
        for (int j = 0; j < CPT; j++) {
            if ((j < 8) || tv) {
                float cur = __fadd_rn(ffv[j], rec[j]);
                float t1  = __fmul_rn(TAU, m[j]);
                float t2  = __fsub_rn(1.0f, s[j]);
                float t3  = __fmul_rn(t1, t2);
                float mn  = __fadd_rn(t3, cur);
                m[j] = mn;
                s[j] = (mn >= 1.0f) ? 1.0f : 0.0f;
            }
        }
        if (tv)
            out[((size_t)b * T_ + t) * NOUT + tid] = s[8];

        __syncthreads();   // protect sm reuse next iteration
    }
}

// ---------------- launch -----------------------------------------------------
extern "C" void kernel_launch(void* const* d_in, const int* in_sizes, int n_in,
                              void* d_out, int out_size) {
    const float* x  = (const float*)d_in[0];   // [B, T, NIN]
    const float* W1 = (const float*)d_in[1];   // [NN, NIN]
    const float* Wr = (const float*)d_in[2];   // [NN, NN]
    float* out = (float*)d_out;                // [B, T, NOUT]

    zero_ctrl_kernel<<<1, 128>>>();
    {
        size_t n = (size_t)MROWS * KP;
        pad_x_kernel<<<(unsigned)((n + 255) / 256), 256>>>(x);
    }
    {
        size_t n = (size_t)KP * NNP;
        pad_w1t_kernel<<<(unsigned)((n + 255) / 256), 256>>>(W1);
    }

    fused_kernel<<<B_ + NHELP, 256>>>(Wr, out);
}